// round 14
// baseline (speedup 1.0000x reference)
#include <cuda_runtime.h>
#include <cstddef>
#include <cstdint>

// Fully TMA-staged FWHT: 32KB bulk loads (double-buffered, mbarrier) AND
// 32KB bulk stores (bulk_group, overlapped with next stage's compute).
// Zero LSU global traffic; HBM sees coarse same-direction 32KB bursts per
// SM instead of finely interleaved LDG/STG -- targets the read/write
// turnaround overhead suspected of pinning R5-R13 at 67-75% DRAM.
// Transpose is done IN PLACE in the consumed input row via XOR swizzle
// (addr r*32 + (c^r): conflict-free both directions in a linear buffer),
// eliminating the padded scratch entirely.
// Compute body = R12 champion: packed f32x2 butterflies + packed fma epilogue.
//
// Math: thread owns 32 elements i = 128k+4lane+b as v[c], c=4k+b.
// FWHT1024 = FWHT32 over c-bits (i bits 0,1,7,8,9)
//          o FWHT32 over lane-bits (i bits 2..6) via in-place XOR transpose.

#define NWARPS 8
#define RPS 8                                   // rows per stage
#define STAGE_FLOATS (RPS * 1024)               // 8192 floats = 32KB
#define MBAR_FLOAT_OFF (3 * STAGE_FLOATS)       // in0, in1, out
#define SMEM_BYTES (MBAR_FLOAT_OFF * 4 + 16)    // 98320 B

__device__ __forceinline__ unsigned long long pk2(float lo, float hi)
{
    unsigned long long r;
    asm("mov.b64 %0, {%1, %2};" : "=l"(r) : "f"(lo), "f"(hi));
    return r;
}
__device__ __forceinline__ void upk2(float& lo, float& hi, unsigned long long p)
{
    asm("mov.b64 {%0, %1}, %2;" : "=f"(lo), "=f"(hi) : "l"(p));
}
__device__ __forceinline__ void pbfly(float* v, int i, int j)
{
    unsigned long long A = pk2(v[2*i], v[2*i+1]);
    unsigned long long B = pk2(v[2*j], v[2*j+1]);
    unsigned long long S, D;
    asm("add.rn.f32x2 %0, %1, %2;" : "=l"(S) : "l"(A), "l"(B));
    asm("sub.rn.f32x2 %0, %1, %2;" : "=l"(D) : "l"(A), "l"(B));
    upk2(v[2*i], v[2*i+1], S);
    upk2(v[2*j], v[2*j+1], D);
}
__device__ __forceinline__ void fwht32(float* v)
{
    #pragma unroll
    for (int q = 0; q < 16; q++) {              // stage m=1: scalar
        float u = v[2*q], w = v[2*q+1];
        v[2*q] = u + w;  v[2*q+1] = u - w;
    }
    #pragma unroll
    for (int mq = 1; mq < 16; mq <<= 1) {       // m=2,4,8,16: packed f32x2
        #pragma unroll
        for (int q = 0; q < 16; q++)
            if ((q & mq) == 0) pbfly(v, q, q | mq);
    }
}

__device__ __forceinline__ void mbar_expect_tx(uint32_t mbar, uint32_t bytes)
{
    asm volatile("mbarrier.arrive.expect_tx.shared::cta.b64 _, [%0], %1;"
                 :: "r"(mbar), "r"(bytes) : "memory");
}
__device__ __forceinline__ void bulk_g2s(uint32_t smem_dst, const void* gmem_src,
                                         uint32_t bytes, uint32_t mbar)
{
    asm volatile("cp.async.bulk.shared::cta.global.mbarrier::complete_tx::bytes "
                 "[%0], [%1], %2, [%3];"
                 :: "r"(smem_dst), "l"(gmem_src), "r"(bytes), "r"(mbar)
                 : "memory");
}
__device__ __forceinline__ void bulk_s2g(void* gmem_dst, uint32_t smem_src,
                                         uint32_t bytes)
{
    asm volatile("cp.async.bulk.global.shared::cta.bulk_group [%0], [%1], %2;"
                 :: "l"(gmem_dst), "r"(smem_src), "r"(bytes) : "memory");
}
__device__ __forceinline__ void mbar_wait(uint32_t mbar, uint32_t parity)
{
    uint32_t done;
    do {
        asm volatile("{\n\t.reg .pred p;\n\t"
                     "mbarrier.try_wait.parity.acquire.cta.shared::cta.b64 p, [%1], %2, 0x989680;\n\t"
                     "selp.b32 %0, 1, 0, p;\n\t}"
                     : "=r"(done) : "r"(mbar), "r"(parity) : "memory");
    } while (!done);
}

__global__ void __launch_bounds__(256, 2)
fwht1024_kernel(const float* __restrict__ x,
                const float* __restrict__ scale,
                const float* __restrict__ shift,
                float* __restrict__ out,
                int nrows, int nstages, int stage_stride)
{
    extern __shared__ float smem[];
    const int tid    = threadIdx.x;
    const int wlocal = tid >> 5;
    const int lane   = tid & 31;

    float* __restrict__ in0  = smem;
    float* __restrict__ in1  = smem + STAGE_FLOATS;
    float* __restrict__ outb = smem + 2 * STAGE_FLOATS;
    const uint32_t mbar_base =
        (uint32_t)__cvta_generic_to_shared(smem + MBAR_FLOAT_OFF);
    const uint32_t mb0 = mbar_base, mb1 = mbar_base + 8;

    // ---- packed register-resident scale*(1/32) and shift ----
    unsigned long long spp[16], sbp[16];
    {
        const float4* __restrict__ sc4 = reinterpret_cast<const float4*>(scale);
        const float4* __restrict__ sh4 = reinterpret_cast<const float4*>(shift);
        const float inv = 0.03125f;             // 1/sqrt(1024)
        #pragma unroll
        for (int k = 0; k < 8; k++) {
            float4 s4 = __ldg(&sc4[k * 32 + lane]);
            float4 h4 = __ldg(&sh4[k * 32 + lane]);
            spp[2*k+0] = pk2(s4.x * inv, s4.y * inv);
            spp[2*k+1] = pk2(s4.z * inv, s4.w * inv);
            sbp[2*k+0] = pk2(h4.x, h4.y);
            sbp[2*k+1] = pk2(h4.z, h4.w);
        }
    }

    if (tid == 0) {
        asm volatile("mbarrier.init.shared::cta.b64 [%0], 1;" :: "r"(mb0) : "memory");
        asm volatile("mbarrier.init.shared::cta.b64 [%0], 1;" :: "r"(mb1) : "memory");
        asm volatile("fence.proxy.async.shared::cta;" ::: "memory");
    }
    __syncthreads();

    int stage = blockIdx.x;

    // ---- prologue: bulk-load first stage into in0 ----
    if (tid == 0 && stage < nstages) {
        const int base = stage * RPS;
        const uint32_t bytes = (uint32_t)min(RPS, nrows - base) * 4096u;
        mbar_expect_tx(mb0, bytes);
        bulk_g2s((uint32_t)__cvta_generic_to_shared(in0),
                 x + (size_t)base * 1024u, bytes, mb0);
    }

    int ph0 = 0, ph1 = 0;
    int it = 0;
    for (; stage < nstages; stage += stage_stride, it++) {
        const int cur = it & 1;
        float* __restrict__ sbuf = cur ? in1 : in0;

        // ---- prefetch next stage into the other (already consumed) buffer --
        const int nstage = stage + stage_stride;
        if (tid == 0 && nstage < nstages) {
            const int nbase = nstage * RPS;
            const uint32_t nbytes = (uint32_t)min(RPS, nrows - nbase) * 4096u;
            mbar_expect_tx(cur ? mb0 : mb1, nbytes);
            bulk_g2s((uint32_t)__cvta_generic_to_shared(cur ? in0 : in1),
                     x + (size_t)nbase * 1024u, nbytes, mb0 + (cur ? 0 : 8));
        }

        // ---- wait for current stage data ----
        if (cur == 0) { mbar_wait(mb0, ph0); ph0 ^= 1; }
        else          { mbar_wait(mb1, ph1); ph1 ^= 1; }

        const int base = stage * RPS;
        const int rows_here = min(RPS, nrows - base);
        float v[32];

        if (wlocal < rows_here) {
            float* __restrict__ srow = sbuf + wlocal * 1024;

            // ---- read row (conflict-free LDS.128) ----
            const float4* __restrict__ r4 =
                reinterpret_cast<const float4*>(srow);
            #pragma unroll
            for (int k = 0; k < 8; k++) {
                float4 t = r4[k * 32 + lane];
                v[4*k+0] = t.x; v[4*k+1] = t.y;
                v[4*k+2] = t.z; v[4*k+3] = t.w;
            }
            __syncwarp();                     // row fully read before scramble

            fwht32(v);                        // bits 0,1,7,8,9

            // ---- in-place XOR-swizzled transpose (CF both directions) ----
            #pragma unroll
            for (int c = 0; c < 32; c++) srow[lane * 32 + (c ^ lane)] = v[c];
            __syncwarp();
            #pragma unroll
            for (int j = 0; j < 32; j++) v[j] = srow[j * 32 + (lane ^ j)];

            fwht32(v);                        // bits 2..6

            // ---- transpose back ----
            __syncwarp();
            #pragma unroll
            for (int j = 0; j < 32; j++) srow[j * 32 + (lane ^ j)] = v[j];
            __syncwarp();
            #pragma unroll
            for (int c = 0; c < 32; c++) v[c] = srow[lane * 32 + (c ^ lane)];
        }

        // ---- previous bulk store must have drained before outb overwrite ----
        if (tid == 0)
            asm volatile("cp.async.bulk.wait_group 0;" ::: "memory");
        __syncthreads();

        if (wlocal < rows_here) {
            // ---- packed fma epilogue -> SMEM out stage (CF STS.128) ----
            float4* __restrict__ o4 =
                reinterpret_cast<float4*>(outb + wlocal * 1024);
            #pragma unroll
            for (int k = 0; k < 8; k++) {
                unsigned long long a01 = pk2(v[4*k+0], v[4*k+1]);
                unsigned long long a23 = pk2(v[4*k+2], v[4*k+3]);
                unsigned long long r01, r23;
                asm("fma.rn.f32x2 %0, %1, %2, %3;"
                    : "=l"(r01) : "l"(a01), "l"(spp[2*k+0]), "l"(sbp[2*k+0]));
                asm("fma.rn.f32x2 %0, %1, %2, %3;"
                    : "=l"(r23) : "l"(a23), "l"(spp[2*k+1]), "l"(sbp[2*k+1]));
                float4 r;
                upk2(r.x, r.y, r01);
                upk2(r.z, r.w, r23);
                o4[k * 32 + lane] = r;
            }
        }
        __syncthreads();                      // outb complete across warps

        // ---- one 32KB bulk store, overlapped with next stage's compute ----
        if (tid == 0) {
            asm volatile("fence.proxy.async.shared::cta;" ::: "memory");
            bulk_s2g(out + (size_t)base * 1024u,
                     (uint32_t)__cvta_generic_to_shared(outb),
                     (uint32_t)rows_here * 4096u);
            asm volatile("cp.async.bulk.commit_group;" ::: "memory");
        }
    }

    if (tid == 0)
        asm volatile("cp.async.bulk.wait_group 0;" ::: "memory");
}

extern "C" void kernel_launch(void* const* d_in, const int* in_sizes, int n_in,
                              void* d_out, int out_size)
{
    const float* x     = (const float*)d_in[0];
    const float* scale = (const float*)d_in[1];
    const float* shift = (const float*)d_in[2];
    float* out = (float*)d_out;

    const int nrows   = in_sizes[0] / 1024;
    const int nstages = (nrows + RPS - 1) / RPS;

    int sms = 148;
    cudaDeviceGetAttribute(&sms, cudaDevAttrMultiProcessorCount, 0);

    cudaFuncSetAttribute(fwht1024_kernel,
                         cudaFuncAttributeMaxDynamicSharedMemorySize,
                         SMEM_BYTES);

    const int blocks = sms * 2;                // 2 CTAs/SM, 96KB smem each
    fwht1024_kernel<<<blocks, 32 * NWARPS, SMEM_BYTES>>>(x, scale, shift, out,
                                                         nrows, nstages, blocks);
}

// round 15
// speedup vs baseline: 1.0873x; 1.0873x over previous
#include <cuda_runtime.h>
#include <cstddef>
#include <cstdint>

// FINAL consolidation. 14-round evidence: DRAM% pinned at 63-75% across
// load-path (LDG/cp.async/TMA), store-path, occupancy, wavefront, ILP and
// instruction-count perturbations => the kernel sits at the B300 path-
// independent LTS/HBM mixed-stream ceiling (~6.2TB/s); 512MB/6.2TB/s ~ 81us
// is the floor and R12 (ncu 81.0) is on it. This round keeps the R12 body
// (best ncu + best DRAM%) and shaves residual issue slots:
//  - transpose row-direction accesses vectorized to 64-bit (pad 33->34 keeps
//    float2 alignment; banks 2lane+2q cover all 32 banks in the natural
//    2 phases; column direction stays scalar conflict-free).
//  - persistent-loop pointers incremented instead of remultiplied.
//
// Structure: one warp per row, persistent grid-stride, 16 warps/SM.
// Thread owns 32 elements i = 128k+4lane+b as v[c], c=4k+b.
// FWHT1024 = FWHT32 over c-bits (i bits 0,1,7,8,9; packed f32x2 butterflies)
//          o FWHT32 over lane-bits (i bits 2..6) via padded-SMEM transpose.
// Epilogue: register-resident packed scale*(1/32), shift; fma.rn.f32x2.

#define NWARPS 8
#define PAD 34                                   // float2-aligned padding

__device__ __forceinline__ unsigned long long pk2(float lo, float hi)
{
    unsigned long long r;
    asm("mov.b64 %0, {%1, %2};" : "=l"(r) : "f"(lo), "f"(hi));
    return r;
}
__device__ __forceinline__ void upk2(float& lo, float& hi, unsigned long long p)
{
    asm("mov.b64 {%0, %1}, %2;" : "=f"(lo), "=f"(hi) : "l"(p));
}
__device__ __forceinline__ void pbfly(float* v, int i, int j)
{
    unsigned long long A = pk2(v[2*i], v[2*i+1]);
    unsigned long long B = pk2(v[2*j], v[2*j+1]);
    unsigned long long S, D;
    asm("add.rn.f32x2 %0, %1, %2;" : "=l"(S) : "l"(A), "l"(B));
    asm("sub.rn.f32x2 %0, %1, %2;" : "=l"(D) : "l"(A), "l"(B));
    upk2(v[2*i], v[2*i+1], S);
    upk2(v[2*j], v[2*j+1], D);
}
__device__ __forceinline__ void fwht32(float* v)
{
    #pragma unroll
    for (int q = 0; q < 16; q++) {               // stage m=1: scalar
        float u = v[2*q], w = v[2*q+1];
        v[2*q] = u + w;  v[2*q+1] = u - w;
    }
    #pragma unroll
    for (int mq = 1; mq < 16; mq <<= 1) {        // m=2,4,8,16: packed f32x2
        #pragma unroll
        for (int q = 0; q < 16; q++)
            if ((q & mq) == 0) pbfly(v, q, q | mq);
    }
}

__global__ void __launch_bounds__(256, 2)
fwht1024_kernel(const float* __restrict__ x,
                const float* __restrict__ scale,
                const float* __restrict__ shift,
                float* __restrict__ out,
                int nrows, int warp_stride)
{
    __shared__ float xch[NWARPS][32 * PAD];      // 4352 B/warp, 34.8 KB/block
    const int wlocal = threadIdx.x >> 5;
    const int lane   = threadIdx.x & 31;
    float*  __restrict__ sm  = xch[wlocal];
    float2* __restrict__ smv = reinterpret_cast<float2*>(sm + lane * PAD);

    // ---- packed register-resident scale*(1/32) and shift ----
    // column of v[4k+b] is element 128k+4lane+b == float4 idx 32k+lane, comp b
    unsigned long long spp[16], sbp[16];
    {
        const float4* __restrict__ sc4 = reinterpret_cast<const float4*>(scale);
        const float4* __restrict__ sh4 = reinterpret_cast<const float4*>(shift);
        const float inv = 0.03125f;              // 1/sqrt(1024)
        #pragma unroll
        for (int k = 0; k < 8; k++) {
            float4 s4 = __ldg(&sc4[k * 32 + lane]);
            float4 h4 = __ldg(&sh4[k * 32 + lane]);
            spp[2*k+0] = pk2(s4.x * inv, s4.y * inv);
            spp[2*k+1] = pk2(s4.z * inv, s4.w * inv);
            sbp[2*k+0] = pk2(h4.x, h4.y);
            sbp[2*k+1] = pk2(h4.z, h4.w);
        }
    }

    const int wid = blockIdx.x * NWARPS + wlocal;
    const float4* __restrict__ xin =
        reinterpret_cast<const float4*>(x) + (size_t)wid * 256u + lane;
    float4* __restrict__ xo =
        reinterpret_cast<float4*>(out) + (size_t)wid * 256u + lane;
    const size_t step = (size_t)warp_stride * 256u;

    for (int row = wid; row < nrows;
         row += warp_stride, xin += step, xo += step) {

        float v[32];

        // ---- coalesced streaming load: float4 index 32k+lane ----
        #pragma unroll
        for (int k = 0; k < 8; k++) {
            float4 t = __ldcs(xin + k * 32);
            v[4*k+0] = t.x; v[4*k+1] = t.y; v[4*k+2] = t.z; v[4*k+3] = t.w;
        }

        // ---- FWHT32 over register index (element bits 0,1,7,8,9) ----
        fwht32(v);

        // ---- transpose: row writes as 64-bit (2-phase, bank-clean),
        //                 column reads scalar (banks lane+2j: CF) ----
        #pragma unroll
        for (int q = 0; q < 16; q++)
            smv[q] = make_float2(v[2*q], v[2*q+1]);
        __syncwarp();
        #pragma unroll
        for (int j = 0; j < 32; j++) v[j] = sm[j * PAD + lane];

        // ---- FWHT32 over new register index (element bits 2..6) ----
        fwht32(v);

        // ---- transpose back: column writes scalar (CF),
        //      row reads as 64-bit (overwrites/reads only own words) ----
        #pragma unroll
        for (int j = 0; j < 32; j++) sm[j * PAD + lane] = v[j];
        __syncwarp();
        #pragma unroll
        for (int q = 0; q < 16; q++) {
            float2 t = smv[q];
            v[2*q] = t.x; v[2*q+1] = t.y;
        }

        // ---- epilogue: packed fma.rn.f32x2 scale/shift, streaming store ----
        #pragma unroll
        for (int k = 0; k < 8; k++) {
            unsigned long long a01 = pk2(v[4*k+0], v[4*k+1]);
            unsigned long long a23 = pk2(v[4*k+2], v[4*k+3]);
            unsigned long long r01, r23;
            asm("fma.rn.f32x2 %0, %1, %2, %3;"
                : "=l"(r01) : "l"(a01), "l"(spp[2*k+0]), "l"(sbp[2*k+0]));
            asm("fma.rn.f32x2 %0, %1, %2, %3;"
                : "=l"(r23) : "l"(a23), "l"(spp[2*k+1]), "l"(sbp[2*k+1]));
            float4 r;
            upk2(r.x, r.y, r01);
            upk2(r.z, r.w, r23);
            __stcs(xo + k * 32, r);
        }
        // next-iter transpose writes touch only words this thread last read: safe
    }
}

extern "C" void kernel_launch(void* const* d_in, const int* in_sizes, int n_in,
                              void* d_out, int out_size)
{
    const float* x     = (const float*)d_in[0];
    const float* scale = (const float*)d_in[1];
    const float* shift = (const float*)d_in[2];
    float* out = (float*)d_out;

    const int nrows = in_sizes[0] / 1024;

    int sms = 148;
    cudaDeviceGetAttribute(&sms, cudaDevAttrMultiProcessorCount, 0);
    const int blocks = sms * 2;                 // 2 CTAs/SM, 16 warps/SM
    const int warp_stride = blocks * NWARPS;    // persistent grid-stride

    fwht1024_kernel<<<blocks, 32 * NWARPS>>>(x, scale, shift, out,
                                             nrows, warp_stride);
}